// round 10
// baseline (speedup 1.0000x reference)
#include <cuda_runtime.h>
#include <cuda_bf16.h>
#include <math.h>

#define Bb 2
#define Ss 2048
#define Dd 1024
#define Hh 16
#define HD 64
#define Mrows (Bb*Ss)          // 4096

__device__ float g_qkv[(size_t)Mrows * 3 * Dd];   // [4096][3072]
__device__ float g_att[(size_t)Mrows * Dd];       // [4096][1024]

// ===========================================================================
// Helpers
// ===========================================================================
__device__ __forceinline__ unsigned smem_u32(const void* p) {
    unsigned a;
    asm("{ .reg .u64 t; cvta.to.shared.u64 t, %1; cvt.u32.u64 %0, t; }"
        : "=r"(a) : "l"(p));
    return a;
}

__device__ __forceinline__ unsigned f2tf(float x) {
    unsigned u;
    asm("cvt.rna.tf32.f32 %0, %1;" : "=r"(u) : "f"(x));
    return u;
}

__device__ __forceinline__ void mma8(float* d, const unsigned* a,
                                     unsigned b0, unsigned b1) {
    asm volatile(
        "mma.sync.aligned.m16n8k8.row.col.f32.tf32.tf32.f32 "
        "{%0,%1,%2,%3}, {%4,%5,%6,%7}, {%8,%9}, {%0,%1,%2,%3};"
        : "+f"(d[0]), "+f"(d[1]), "+f"(d[2]), "+f"(d[3])
        : "r"(a[0]), "r"(a[1]), "r"(a[2]), "r"(a[3]), "r"(b0), "r"(b1));
}

__device__ __forceinline__ void mmabf(float* d, const unsigned* a,
                                      unsigned b0, unsigned b1) {
    asm volatile(
        "mma.sync.aligned.m16n8k16.row.col.f32.bf16.bf16.f32 "
        "{%0,%1,%2,%3}, {%4,%5,%6,%7}, {%8,%9}, {%0,%1,%2,%3};"
        : "+f"(d[0]), "+f"(d[1]), "+f"(d[2]), "+f"(d[3])
        : "r"(a[0]), "r"(a[1]), "r"(a[2]), "r"(a[3]), "r"(b0), "r"(b1));
}

__device__ __forceinline__ void ldsm4(unsigned& r0, unsigned& r1,
                                      unsigned& r2, unsigned& r3,
                                      unsigned addr) {
    asm volatile("ldmatrix.sync.aligned.m8n8.x4.shared.b16 {%0,%1,%2,%3}, [%4];"
                 : "=r"(r0), "=r"(r1), "=r"(r2), "=r"(r3) : "r"(addr));
}

__device__ __forceinline__ unsigned short bfr(float x) {
    unsigned short u;
    asm("cvt.rn.bf16.f32 %0, %1;" : "=h"(u) : "f"(x));
    return u;
}
__device__ __forceinline__ float bff(unsigned short u) {
    return __uint_as_float(((unsigned)u) << 16);
}
// Split (x,y) into packed bf16 hi pair + bf16 lo (residual) pair.
__device__ __forceinline__ void split2(float x, float y,
                                       unsigned& hi, unsigned& lo) {
    unsigned short hx = bfr(x), hy = bfr(y);
    unsigned short lx = bfr(x - bff(hx)), ly = bfr(y - bff(hy));
    hi = (unsigned)hx | ((unsigned)hy << 16);
    lo = (unsigned)lx | ((unsigned)ly << 16);
}

// ===========================================================================
// bf16 mma.sync GEMM, 3-term split (AhBh + AhBl + AlBh), err ~1e-5:
//   C[M,N] = A[M,K] @ B[K,N] + bias
// Tile 128x128x32, 512 threads (16 warps, 4x4 -> 32x32 warp tiles),
// double-buffered SMEM; k-major bf16 rows, pitch 80B (conflict-free ldmatrix).
// Per buffer: Ah, Al, Bh, Bl each 128 rows x 80B = 10240 B.
// ===========================================================================
#define BPITCH 80
#define TERMB  (128 * BPITCH)       // 10240 B
#define GBUF   (4 * TERMB)          // 40960 B
#define GEMM_SMEM_BYTES (2 * GBUF)  // 81920 B

struct PrefG {
    float4 a0, a1;   // A row r, k c8..c8+7
    float  b[8];     // B col n, k kq..kq+7
};

__device__ __forceinline__ void g_load(const float* __restrict__ A,
                                       const float* __restrict__ Bm,
                                       int K, int N, int row0, int col0, int k0,
                                       int r, int c8, int nn, int kq, PrefG& p) {
    const float* ap = A + (size_t)(row0 + r) * K + k0 + c8;
    p.a0 = *(const float4*)ap;
    p.a1 = *(const float4*)(ap + 4);
    const float* bp = Bm + (size_t)(k0 + kq) * N + col0 + nn;
    #pragma unroll
    for (int i = 0; i < 8; i++) p.b[i] = bp[(size_t)i * N];
}

__device__ __forceinline__ void s_store(char* __restrict__ buf,
                                        int r, int c8, int nn, int kq,
                                        const PrefG& p) {
    unsigned h0, l0, h1, l1, h2, l2, h3, l3;
    split2(p.a0.x, p.a0.y, h0, l0);
    split2(p.a0.z, p.a0.w, h1, l1);
    split2(p.a1.x, p.a1.y, h2, l2);
    split2(p.a1.z, p.a1.w, h3, l3);
    *(uint4*)(buf + r * BPITCH + c8 * 2)         = make_uint4(h0, h1, h2, h3);
    *(uint4*)(buf + TERMB + r * BPITCH + c8 * 2) = make_uint4(l0, l1, l2, l3);

    unsigned bh0, bl0, bh1, bl1, bh2, bl2, bh3, bl3;
    split2(p.b[0], p.b[1], bh0, bl0);
    split2(p.b[2], p.b[3], bh1, bl1);
    split2(p.b[4], p.b[5], bh2, bl2);
    split2(p.b[6], p.b[7], bh3, bl3);
    *(uint4*)(buf + 2 * TERMB + nn * BPITCH + kq * 2) = make_uint4(bh0, bh1, bh2, bh3);
    *(uint4*)(buf + 3 * TERMB + nn * BPITCH + kq * 2) = make_uint4(bl0, bl1, bl2, bl3);
}

__global__ __launch_bounds__(512, 1)
void gemm_bf16(const float* __restrict__ A, const float* __restrict__ Bm,
               const float* __restrict__ bias, float* __restrict__ C,
               int M, int N, int K) {
    extern __shared__ char smc[];
    const unsigned sbase = smem_u32(smc);
    const int tid = threadIdx.x;
    const int lane = tid & 31, wid = tid >> 5;
    const int warpM = wid & 3, warpN = wid >> 2;
    const int gr = lane >> 2, tg = lane & 3;
    const int row0 = blockIdx.y * 128, col0 = blockIdx.x * 128;

    const int r = tid >> 2, c8 = (tid & 3) * 8;
    const int nn = tid & 127, kq = (tid >> 7) * 8;

    // ldmatrix lane address components (fixed per thread)
    const int lrow = lane & 15;
    const int lcol = (lane >> 4) * 8;   // +8 k for upper half-warp

    float acc[2][4][4];
    #pragma unroll
    for (int mi = 0; mi < 2; mi++)
        #pragma unroll
        for (int ni = 0; ni < 4; ni++)
            #pragma unroll
            for (int q = 0; q < 4; q++) acc[mi][ni][q] = 0.f;

    const int NT = K >> 5;
    PrefG p;
    g_load(A, Bm, K, N, row0, col0, 0, r, c8, nn, kq, p);
    s_store(smc, r, c8, nn, kq, p);
    __syncthreads();

    for (int t = 0; t < NT; t++) {
        const bool more = (t + 1 < NT);
        if (more) g_load(A, Bm, K, N, row0, col0, (t + 1) << 5, r, c8, nn, kq, p);

        const unsigned bufu = sbase + (t & 1) * GBUF;
        #pragma unroll
        for (int kst = 0; kst < 2; kst++) {
            const unsigned kb = (kst * 16 + lcol) * 2;
            unsigned ah[2][4], al[2][4];
            #pragma unroll
            for (int mi = 0; mi < 2; mi++) {
                const unsigned ad =
                    bufu + (warpM * 32 + mi * 16 + lrow) * BPITCH + kb;
                ldsm4(ah[mi][0], ah[mi][1], ah[mi][2], ah[mi][3], ad);
                ldsm4(al[mi][0], al[mi][1], al[mi][2], al[mi][3], ad + TERMB);
            }
            unsigned bh[4][2], bl[4][2];
            #pragma unroll
            for (int pp = 0; pp < 2; pp++) {
                const unsigned bd = bufu + 2 * TERMB +
                    (warpN * 32 + pp * 16 + lrow) * BPITCH + kb;
                unsigned q0, q1, q2, q3;
                ldsm4(q0, q1, q2, q3, bd);
                bh[2 * pp][0] = q0; bh[2 * pp][1] = q2;
                bh[2 * pp + 1][0] = q1; bh[2 * pp + 1][1] = q3;
                ldsm4(q0, q1, q2, q3, bd + TERMB);
                bl[2 * pp][0] = q0; bl[2 * pp][1] = q2;
                bl[2 * pp + 1][0] = q1; bl[2 * pp + 1][1] = q3;
            }
            #pragma unroll
            for (int mi = 0; mi < 2; mi++)
                #pragma unroll
                for (int ni = 0; ni < 4; ni++) {
                    mmabf(acc[mi][ni], ah[mi], bh[ni][0], bh[ni][1]);
                    mmabf(acc[mi][ni], ah[mi], bl[ni][0], bl[ni][1]);
                    mmabf(acc[mi][ni], al[mi], bh[ni][0], bh[ni][1]);
                }
        }

        if (more) s_store(smc + ((t + 1) & 1) * GBUF, r, c8, nn, kq, p);
        __syncthreads();
    }

    #pragma unroll
    for (int mi = 0; mi < 2; mi++) {
        const int rr = row0 + warpM * 32 + mi * 16 + gr;
        #pragma unroll
        for (int ni = 0; ni < 4; ni++) {
            const int c = col0 + warpN * 32 + ni * 8 + tg * 2;
            const float bx = bias[c], by = bias[c + 1];
            float2 o0, o1;
            o0.x = acc[mi][ni][0] + bx;
            o0.y = acc[mi][ni][1] + by;
            o1.x = acc[mi][ni][2] + bx;
            o1.y = acc[mi][ni][3] + by;
            *(float2*)&C[(size_t)rr * N + c] = o0;
            *(float2*)&C[(size_t)(rr + 8) * N + c] = o1;
        }
    }
}

// ===========================================================================
// Flash attention with mma.sync tf32 (unchanged from R9 — passing, ~265us).
// ===========================================================================
#define AP 68
#define KT 64
#define ATT_SMEM_FLOATS (128 * AP + 8 * 16 * AP + 64)
#define ATT_SMEM_BYTES (ATT_SMEM_FLOATS * 4)

__global__ __launch_bounds__(256, 1)
void flash_mma(const float* __restrict__ qkv, const float* __restrict__ mask,
               float* __restrict__ att) {
    extern __shared__ float smf[];
    float* Ks = smf;                        // [j][d] pitch AP (64 rows)
    float* Vs = smf + 64 * AP;              // [d][j] pitch AP (64 rows)
    float* Pm = smf + 128 * AP;             // per-warp [16][AP]
    float* Lm = smf + 128 * AP + 8 * 16 * AP;

    const int it = (gridDim.x - 1) - blockIdx.x;   // heavy tiles first
    const int h  = blockIdx.y;
    const int b  = blockIdx.z;
    const int tid  = threadIdx.x;
    const int wid  = tid >> 5;
    const int lane = tid & 31;
    const int gr = lane >> 2, tg = lane & 3;
    const int i0 = it * 128 + wid * 16 + gr;       // thread's first q row
    float* Pw = Pm + wid * (16 * AP);

    // ---- Stage Q tile [128][64] into smf (pitch AP), then frags to regs ----
    {
        const float* qb = qkv + ((size_t)(b * Ss + it * 128) * 3) * Dd + h * HD;
        #pragma unroll
        for (int p = 0; p < 8; p++) {
            int g = p * 256 + tid;
            int rq = g >> 4, c4 = g & 15;
            float4 v = *(const float4*)(qb + (size_t)rq * 3072 + c4 * 4);
            *(float4*)&smf[rq * AP + c4 * 4] = v;
        }
    }
    __syncthreads();
    unsigned qf[8][4];
    {
        const int rb = wid * 16 + gr;
        #pragma unroll
        for (int kb = 0; kb < 8; kb++) {
            qf[kb][0] = f2tf(smf[rb * AP + kb * 8 + tg]);
            qf[kb][1] = f2tf(smf[(rb + 8) * AP + kb * 8 + tg]);
            qf[kb][2] = f2tf(smf[rb * AP + kb * 8 + tg + 4]);
            qf[kb][3] = f2tf(smf[(rb + 8) * AP + kb * 8 + tg + 4]);
        }
    }

    float oacc[8][4];
    #pragma unroll
    for (int nb = 0; nb < 8; nb++)
        #pragma unroll
        for (int q = 0; q < 4; q++) oacc[nb][q] = 0.f;
    float m0 = -1e30f, m1 = -1e30f, l0 = 0.f, l1 = 0.f;

    const int ntiles = 2 * it + 2;

    for (int jt = 0; jt < ntiles; jt++) {
        const int j0 = jt * KT;
        __syncthreads();   // previous tile fully consumed
        // ---- K tile [j][d], tf32-rounded ----
        {
            const float* kb_ = qkv + ((size_t)(b * Ss + j0) * 3 + 1) * Dd + h * HD;
            #pragma unroll
            for (int p = 0; p < 4; p++) {
                int g = p * 256 + tid;
                int rq = g >> 4, c4 = g & 15;
                float4 v = *(const float4*)(kb_ + (size_t)rq * 3072 + c4 * 4);
                uint4 u;
                u.x = f2tf(v.x); u.y = f2tf(v.y);
                u.z = f2tf(v.z); u.w = f2tf(v.w);
                *(uint4*)&Ks[rq * AP + c4 * 4] = u;
            }
        }
        // ---- V tile transposed: warp w owns d in [8w, 8w+8), ALL 64 j ----
        {
            const float* vb = qkv + ((size_t)(b * Ss + j0) * 3 + 2) * Dd + h * HD
                              + wid * 8;
            #pragma unroll
            for (int jh = 0; jh < 2; jh++) {
                const int j = jh * 32 + lane;
                float4 v0 = *(const float4*)(vb + (size_t)j * 3072);
                float4 v1 = *(const float4*)(vb + (size_t)j * 3072 + 4);
                const float* vf0 = &v0.x;
                const float* vf1 = &v1.x;
                #pragma unroll
                for (int ii = 0; ii < 4; ii++) {
                    Vs[(wid * 8 + ii) * AP + j] =
                        __uint_as_float(f2tf(vf0[ii]));
                    Vs[(wid * 8 + 4 + ii) * AP + j] =
                        __uint_as_float(f2tf(vf1[ii]));
                }
            }
        }
        if (tid < KT) Lm[tid] = __logf(mask[b * Ss + j0 + tid]);
        __syncthreads();

        // ---- S = Q K^T (64 MMAs) ----
        float sacc[8][4];
        #pragma unroll
        for (int nb = 0; nb < 8; nb++) {
            sacc[nb][0] = sacc[nb][1] = sacc[nb][2] = sacc[nb][3] = 0.f;
            #pragma unroll
            for (int kb = 0; kb < 8; kb++) {
                unsigned b0 = __float_as_uint(Ks[(nb * 8 + gr) * AP + kb * 8 + tg]);
                unsigned b1 = __float_as_uint(Ks[(nb * 8 + gr) * AP + kb * 8 + tg + 4]);
                mma8(sacc[nb], qf[kb], b0, b1);
            }
        }

        // ---- scale + logmask + causal ----
        const bool partial = (j0 + KT - 1 > i0);   // needs per-element mask
        #pragma unroll
        for (int nb = 0; nb < 8; nb++) {
            const int c = nb * 8 + 2 * tg;
            const float lmx = Lm[c], lmy = Lm[c + 1];
            sacc[nb][0] = sacc[nb][0] * 0.125f + lmx;
            sacc[nb][1] = sacc[nb][1] * 0.125f + lmy;
            sacc[nb][2] = sacc[nb][2] * 0.125f + lmx;
            sacc[nb][3] = sacc[nb][3] * 0.125f + lmy;
            if (partial) {
                const int jcx = j0 + c, jcy = j0 + c + 1;
                if (jcx > i0)     sacc[nb][0] = -1e30f;
                if (jcy > i0)     sacc[nb][1] = -1e30f;
                if (jcx > i0 + 8) sacc[nb][2] = -1e30f;
                if (jcy > i0 + 8) sacc[nb][3] = -1e30f;
            }
        }

        // ---- online softmax (rows i0, i0+8) ----
        float mx0 = -1e30f, mx1 = -1e30f;
        #pragma unroll
        for (int nb = 0; nb < 8; nb++) {
            mx0 = fmaxf(mx0, fmaxf(sacc[nb][0], sacc[nb][1]));
            mx1 = fmaxf(mx1, fmaxf(sacc[nb][2], sacc[nb][3]));
        }
        mx0 = fmaxf(mx0, __shfl_xor_sync(0xffffffffu, mx0, 1));
        mx0 = fmaxf(mx0, __shfl_xor_sync(0xffffffffu, mx0, 2));
        mx1 = fmaxf(mx1, __shfl_xor_sync(0xffffffffu, mx1, 1));
        mx1 = fmaxf(mx1, __shfl_xor_sync(0xffffffffu, mx1, 2));
        const float nm0 = fmaxf(m0, mx0), nm1 = fmaxf(m1, mx1);
        const float c0 = __expf(m0 - nm0), c1 = __expf(m1 - nm1);
        m0 = nm0; m1 = nm1;

        float ls0 = 0.f, ls1 = 0.f;
        #pragma unroll
        for (int nb = 0; nb < 8; nb++) {
            const float p0 = __expf(sacc[nb][0] - m0);
            const float p1 = __expf(sacc[nb][1] - m0);
            const float p2 = __expf(sacc[nb][2] - m1);
            const float p3 = __expf(sacc[nb][3] - m1);
            ls0 += p0 + p1;
            ls1 += p2 + p3;
            const int c = nb * 8 + 2 * tg;
            float2 w0, w1;
            w0.x = __uint_as_float(f2tf(p0));
            w0.y = __uint_as_float(f2tf(p1));
            w1.x = __uint_as_float(f2tf(p2));
            w1.y = __uint_as_float(f2tf(p3));
            *(float2*)&Pw[gr * AP + c] = w0;
            *(float2*)&Pw[(gr + 8) * AP + c] = w1;
        }
        ls0 += __shfl_xor_sync(0xffffffffu, ls0, 1);
        ls0 += __shfl_xor_sync(0xffffffffu, ls0, 2);
        ls1 += __shfl_xor_sync(0xffffffffu, ls1, 1);
        ls1 += __shfl_xor_sync(0xffffffffu, ls1, 2);
        l0 = l0 * c0 + ls0;
        l1 = l1 * c1 + ls1;
        #pragma unroll
        for (int nb = 0; nb < 8; nb++) {
            oacc[nb][0] *= c0; oacc[nb][1] *= c0;
            oacc[nb][2] *= c1; oacc[nb][3] *= c1;
        }
        __syncwarp();

        // ---- O += P V (64 MMAs) ----
        #pragma unroll
        for (int kb = 0; kb < 8; kb++) {
            unsigned af[4];
            af[0] = __float_as_uint(Pw[gr * AP + kb * 8 + tg]);
            af[1] = __float_as_uint(Pw[(gr + 8) * AP + kb * 8 + tg]);
            af[2] = __float_as_uint(Pw[gr * AP + kb * 8 + tg + 4]);
            af[3] = __float_as_uint(Pw[(gr + 8) * AP + kb * 8 + tg + 4]);
            #pragma unroll
            for (int nb = 0; nb < 8; nb++) {
                unsigned b0 = __float_as_uint(Vs[(nb * 8 + gr) * AP + kb * 8 + tg]);
                unsigned b1 = __float_as_uint(Vs[(nb * 8 + gr) * AP + kb * 8 + tg + 4]);
                mma8(oacc[nb], af, b0, b1);
            }
        }
    }

    // ---- epilogue ----
    const float inv0 = 1.f / l0, inv1 = 1.f / l1;
    float* out0 = att + (size_t)(b * Ss + i0) * Dd + h * HD;
    float* out1 = out0 + (size_t)8 * Dd;
    #pragma unroll
    for (int nb = 0; nb < 8; nb++) {
        const int c = nb * 8 + 2 * tg;
        float2 o0, o1;
        o0.x = oacc[nb][0] * inv0;
        o0.y = oacc[nb][1] * inv0;
        o1.x = oacc[nb][2] * inv1;
        o1.y = oacc[nb][3] * inv1;
        *(float2*)&out0[c] = o0;
        *(float2*)&out1[c] = o1;
    }
}

// ===========================================================================
// Launch
// ===========================================================================
extern "C" void kernel_launch(void* const* d_in, const int* in_sizes, int n_in,
                              void* d_out, int out_size) {
    const float* x     = (const float*)d_in[0];
    const float* mask  = (const float*)d_in[1];
    const float* W_qkv = (const float*)d_in[2];
    const float* b_qkv = (const float*)d_in[3];
    const float* W_o   = (const float*)d_in[4];
    const float* b_o   = (const float*)d_in[5];
    float* out = (float*)d_out;

    float* qkv_ptr = nullptr;
    float* att_ptr = nullptr;
    cudaGetSymbolAddress((void**)&qkv_ptr, g_qkv);
    cudaGetSymbolAddress((void**)&att_ptr, g_att);

    cudaFuncSetAttribute(gemm_bf16, cudaFuncAttributeMaxDynamicSharedMemorySize,
                         GEMM_SMEM_BYTES);
    cudaFuncSetAttribute(flash_mma, cudaFuncAttributeMaxDynamicSharedMemorySize,
                         ATT_SMEM_BYTES);

    // 1) QKV projection
    gemm_bf16<<<dim3(3 * Dd / 128, Mrows / 128), 512, GEMM_SMEM_BYTES>>>(
        x, W_qkv, b_qkv, qkv_ptr, Mrows, 3 * Dd, Dd);

    // 2) Flash attention (tensorized)
    flash_mma<<<dim3(Ss / 128, Hh, Bb), 256, ATT_SMEM_BYTES>>>(
        qkv_ptr, mask, att_ptr);

    // 3) Output projection
    gemm_bf16<<<dim3(Dd / 128, Mrows / 128), 512, GEMM_SMEM_BYTES>>>(
        att_ptr, W_o, b_o, out, Mrows, Dd, Dd);
}

// round 11
// speedup vs baseline: 1.8836x; 1.8836x over previous
#include <cuda_runtime.h>
#include <math.h>

#define Bb 2
#define Ss 2048
#define Dd 1024
#define Hh 16
#define HD 64
#define Mrows (Bb*Ss)          // 4096

__device__ float g_qkv[(size_t)Mrows * 3 * Dd];   // [4096][3072]
__device__ float g_att[(size_t)Mrows * Dd];       // [4096][1024]

// ===========================================================================
// Helpers
// ===========================================================================
__device__ __forceinline__ unsigned f2tf(float x) {
    unsigned u;
    asm("cvt.rna.tf32.f32 %0, %1;" : "=r"(u) : "f"(x));
    return u;
}

__device__ __forceinline__ void mma8(float* d, const unsigned* a,
                                     unsigned b0, unsigned b1) {
    asm volatile(
        "mma.sync.aligned.m16n8k8.row.col.f32.tf32.tf32.f32 "
        "{%0,%1,%2,%3}, {%4,%5,%6,%7}, {%8,%9}, {%0,%1,%2,%3};"
        : "+f"(d[0]), "+f"(d[1]), "+f"(d[2]), "+f"(d[3])
        : "r"(a[0]), "r"(a[1]), "r"(a[2]), "r"(a[3]), "r"(b0), "r"(b1));
}

// ===========================================================================
// Plain tf32 mma.sync GEMM (1-term, both operands rounded once):
//   C[M,N] = A[M,K] @ B[K,N] + bias     rel err ~2e-4 rms
// Tile 128x128x32, 512 threads (16 warps, 4x4 -> 32x32 warp tiles),
// double-buffered SMEM, pitch-36 rows (conflict-free frag LDS + STS.128).
// Per buffer: A[128][36], B[128][36] ([n][k]) words.
// ===========================================================================
#define GP 36
#define TSZ (128 * GP)          // 4608 words
#define BUFW (2 * TSZ)          // 9216 words per buffer
#define GEMM_SMEM_BYTES (2 * BUFW * 4)   // 73728 B

struct Pref {
    float4 a0, a1;   // A row r, k c8..c8+7
    float  b[8];     // B col n, k kq..kq+7
};

__device__ __forceinline__ void g_load(const float* __restrict__ A,
                                       const float* __restrict__ Bm,
                                       int K, int N, int row0, int col0, int k0,
                                       int r, int c8, int nn, int kq, Pref& p) {
    const float* ap = A + (size_t)(row0 + r) * K + k0 + c8;
    p.a0 = *(const float4*)ap;
    p.a1 = *(const float4*)(ap + 4);
    const float* bp = Bm + (size_t)(k0 + kq) * N + col0 + nn;
    #pragma unroll
    for (int i = 0; i < 8; i++) p.b[i] = bp[(size_t)i * N];
}

__device__ __forceinline__ void s_store(unsigned* __restrict__ sm,
                                        int r, int c8, int nn, int kq,
                                        const Pref& p) {
    uint4 q0, q1;
    q0.x = f2tf(p.a0.x); q0.y = f2tf(p.a0.y);
    q0.z = f2tf(p.a0.z); q0.w = f2tf(p.a0.w);
    q1.x = f2tf(p.a1.x); q1.y = f2tf(p.a1.y);
    q1.z = f2tf(p.a1.z); q1.w = f2tf(p.a1.w);
    *(uint4*)&sm[r * GP + c8]     = q0;
    *(uint4*)&sm[r * GP + c8 + 4] = q1;

    uint4 b0, b1;
    b0.x = f2tf(p.b[0]); b0.y = f2tf(p.b[1]);
    b0.z = f2tf(p.b[2]); b0.w = f2tf(p.b[3]);
    b1.x = f2tf(p.b[4]); b1.y = f2tf(p.b[5]);
    b1.z = f2tf(p.b[6]); b1.w = f2tf(p.b[7]);
    *(uint4*)&sm[TSZ + nn * GP + kq]     = b0;
    *(uint4*)&sm[TSZ + nn * GP + kq + 4] = b1;
}

__global__ __launch_bounds__(512, 1)
void gemm_tf32(const float* __restrict__ A, const float* __restrict__ Bm,
               const float* __restrict__ bias, float* __restrict__ C,
               int M, int N, int K) {
    extern __shared__ unsigned sm[];
    const int tid = threadIdx.x;
    const int lane = tid & 31, wid = tid >> 5;
    const int warpM = wid & 3, warpN = wid >> 2;
    const int gr = lane >> 2, tg = lane & 3;
    const int row0 = blockIdx.y * 128, col0 = blockIdx.x * 128;

    const int r = tid >> 2, c8 = (tid & 3) * 8;
    const int nn = tid & 127, kq = (tid >> 7) * 8;

    float acc[2][4][4];
    #pragma unroll
    for (int mi = 0; mi < 2; mi++)
        #pragma unroll
        for (int ni = 0; ni < 4; ni++)
            #pragma unroll
            for (int q = 0; q < 4; q++) acc[mi][ni][q] = 0.f;

    const int NT = K >> 5;
    Pref p;
    g_load(A, Bm, K, N, row0, col0, 0, r, c8, nn, kq, p);
    s_store(sm, r, c8, nn, kq, p);
    __syncthreads();

    for (int t = 0; t < NT; t++) {
        const bool more = (t + 1 < NT);
        if (more) g_load(A, Bm, K, N, row0, col0, (t + 1) << 5, r, c8, nn, kq, p);

        const unsigned* base = sm + (t & 1) * BUFW;
        #pragma unroll
        for (int ks = 0; ks < 4; ks++) {
            const int acol = ks * 8 + tg;
            unsigned ah[2][4];
            #pragma unroll
            for (int mi = 0; mi < 2; mi++) {
                const int rb = warpM * 32 + mi * 16 + gr;
                ah[mi][0] = base[rb * GP + acol];
                ah[mi][1] = base[(rb + 8) * GP + acol];
                ah[mi][2] = base[rb * GP + acol + 4];
                ah[mi][3] = base[(rb + 8) * GP + acol + 4];
            }
            unsigned bh[4][2];
            #pragma unroll
            for (int ni = 0; ni < 4; ni++) {
                const int nb = warpN * 32 + ni * 8 + gr;
                bh[ni][0] = base[TSZ + nb * GP + acol];
                bh[ni][1] = base[TSZ + nb * GP + acol + 4];
            }
            #pragma unroll
            for (int mi = 0; mi < 2; mi++)
                #pragma unroll
                for (int ni = 0; ni < 4; ni++)
                    mma8(acc[mi][ni], ah[mi], bh[ni][0], bh[ni][1]);
        }

        if (more) s_store(sm + ((t + 1) & 1) * BUFW, r, c8, nn, kq, p);
        __syncthreads();
    }

    #pragma unroll
    for (int mi = 0; mi < 2; mi++) {
        const int rr = row0 + warpM * 32 + mi * 16 + gr;
        #pragma unroll
        for (int ni = 0; ni < 4; ni++) {
            const int c = col0 + warpN * 32 + ni * 8 + tg * 2;
            const float bx = bias[c], by = bias[c + 1];
            float2 o0, o1;
            o0.x = acc[mi][ni][0] + bx;
            o0.y = acc[mi][ni][1] + by;
            o1.x = acc[mi][ni][2] + bx;
            o1.y = acc[mi][ni][3] + by;
            *(float2*)&C[(size_t)rr * N + c] = o0;
            *(float2*)&C[(size_t)(rr + 8) * N + c] = o1;
        }
    }
}

// ===========================================================================
// Flash attention with mma.sync tf32 (unchanged from R9 — passing, ~265us).
// ===========================================================================
#define AP 68
#define KT 64
#define ATT_SMEM_FLOATS (128 * AP + 8 * 16 * AP + 64)
#define ATT_SMEM_BYTES (ATT_SMEM_FLOATS * 4)

__global__ __launch_bounds__(256, 1)
void flash_mma(const float* __restrict__ qkv, const float* __restrict__ mask,
               float* __restrict__ att) {
    extern __shared__ float smf[];
    float* Ks = smf;                        // [j][d] pitch AP (64 rows)
    float* Vs = smf + 64 * AP;              // [d][j] pitch AP (64 rows)
    float* Pm = smf + 128 * AP;             // per-warp [16][AP]
    float* Lm = smf + 128 * AP + 8 * 16 * AP;

    const int it = (gridDim.x - 1) - blockIdx.x;   // heavy tiles first
    const int h  = blockIdx.y;
    const int b  = blockIdx.z;
    const int tid  = threadIdx.x;
    const int wid  = tid >> 5;
    const int lane = tid & 31;
    const int gr = lane >> 2, tg = lane & 3;
    const int i0 = it * 128 + wid * 16 + gr;       // thread's first q row
    float* Pw = Pm + wid * (16 * AP);

    // ---- Stage Q tile [128][64] into smf (pitch AP), then frags to regs ----
    {
        const float* qb = qkv + ((size_t)(b * Ss + it * 128) * 3) * Dd + h * HD;
        #pragma unroll
        for (int p = 0; p < 8; p++) {
            int g = p * 256 + tid;
            int rq = g >> 4, c4 = g & 15;
            float4 v = *(const float4*)(qb + (size_t)rq * 3072 + c4 * 4);
            *(float4*)&smf[rq * AP + c4 * 4] = v;
        }
    }
    __syncthreads();
    unsigned qf[8][4];
    {
        const int rb = wid * 16 + gr;
        #pragma unroll
        for (int kb = 0; kb < 8; kb++) {
            qf[kb][0] = f2tf(smf[rb * AP + kb * 8 + tg]);
            qf[kb][1] = f2tf(smf[(rb + 8) * AP + kb * 8 + tg]);
            qf[kb][2] = f2tf(smf[rb * AP + kb * 8 + tg + 4]);
            qf[kb][3] = f2tf(smf[(rb + 8) * AP + kb * 8 + tg + 4]);
        }
    }

    float oacc[8][4];
    #pragma unroll
    for (int nb = 0; nb < 8; nb++)
        #pragma unroll
        for (int q = 0; q < 4; q++) oacc[nb][q] = 0.f;
    float m0 = -1e30f, m1 = -1e30f, l0 = 0.f, l1 = 0.f;

    const int ntiles = 2 * it + 2;

    for (int jt = 0; jt < ntiles; jt++) {
        const int j0 = jt * KT;
        __syncthreads();   // previous tile fully consumed
        // ---- K tile [j][d], tf32-rounded ----
        {
            const float* kb_ = qkv + ((size_t)(b * Ss + j0) * 3 + 1) * Dd + h * HD;
            #pragma unroll
            for (int p = 0; p < 4; p++) {
                int g = p * 256 + tid;
                int rq = g >> 4, c4 = g & 15;
                float4 v = *(const float4*)(kb_ + (size_t)rq * 3072 + c4 * 4);
                uint4 u;
                u.x = f2tf(v.x); u.y = f2tf(v.y);
                u.z = f2tf(v.z); u.w = f2tf(v.w);
                *(uint4*)&Ks[rq * AP + c4 * 4] = u;
            }
        }
        // ---- V tile transposed: warp w owns d in [8w, 8w+8), ALL 64 j ----
        {
            const float* vb = qkv + ((size_t)(b * Ss + j0) * 3 + 2) * Dd + h * HD
                              + wid * 8;
            #pragma unroll
            for (int jh = 0; jh < 2; jh++) {
                const int j = jh * 32 + lane;
                float4 v0 = *(const float4*)(vb + (size_t)j * 3072);
                float4 v1 = *(const float4*)(vb + (size_t)j * 3072 + 4);
                const float* vf0 = &v0.x;
                const float* vf1 = &v1.x;
                #pragma unroll
                for (int ii = 0; ii < 4; ii++) {
                    Vs[(wid * 8 + ii) * AP + j] =
                        __uint_as_float(f2tf(vf0[ii]));
                    Vs[(wid * 8 + 4 + ii) * AP + j] =
                        __uint_as_float(f2tf(vf1[ii]));
                }
            }
        }
        if (tid < KT) Lm[tid] = __logf(mask[b * Ss + j0 + tid]);
        __syncthreads();

        // ---- S = Q K^T (64 MMAs) ----
        float sacc[8][4];
        #pragma unroll
        for (int nb = 0; nb < 8; nb++) {
            sacc[nb][0] = sacc[nb][1] = sacc[nb][2] = sacc[nb][3] = 0.f;
            #pragma unroll
            for (int kb = 0; kb < 8; kb++) {
                unsigned b0 = __float_as_uint(Ks[(nb * 8 + gr) * AP + kb * 8 + tg]);
                unsigned b1 = __float_as_uint(Ks[(nb * 8 + gr) * AP + kb * 8 + tg + 4]);
                mma8(sacc[nb], qf[kb], b0, b1);
            }
        }

        // ---- scale + logmask + causal ----
        const bool partial = (j0 + KT - 1 > i0);   // needs per-element mask
        #pragma unroll
        for (int nb = 0; nb < 8; nb++) {
            const int c = nb * 8 + 2 * tg;
            const float lmx = Lm[c], lmy = Lm[c + 1];
            sacc[nb][0] = sacc[nb][0] * 0.125f + lmx;
            sacc[nb][1] = sacc[nb][1] * 0.125f + lmy;
            sacc[nb][2] = sacc[nb][2] * 0.125f + lmx;
            sacc[nb][3] = sacc[nb][3] * 0.125f + lmy;
            if (partial) {
                const int jcx = j0 + c, jcy = j0 + c + 1;
                if (jcx > i0)     sacc[nb][0] = -1e30f;
                if (jcy > i0)     sacc[nb][1] = -1e30f;
                if (jcx > i0 + 8) sacc[nb][2] = -1e30f;
                if (jcy > i0 + 8) sacc[nb][3] = -1e30f;
            }
        }

        // ---- online softmax (rows i0, i0+8) ----
        float mx0 = -1e30f, mx1 = -1e30f;
        #pragma unroll
        for (int nb = 0; nb < 8; nb++) {
            mx0 = fmaxf(mx0, fmaxf(sacc[nb][0], sacc[nb][1]));
            mx1 = fmaxf(mx1, fmaxf(sacc[nb][2], sacc[nb][3]));
        }
        mx0 = fmaxf(mx0, __shfl_xor_sync(0xffffffffu, mx0, 1));
        mx0 = fmaxf(mx0, __shfl_xor_sync(0xffffffffu, mx0, 2));
        mx1 = fmaxf(mx1, __shfl_xor_sync(0xffffffffu, mx1, 1));
        mx1 = fmaxf(mx1, __shfl_xor_sync(0xffffffffu, mx1, 2));
        const float nm0 = fmaxf(m0, mx0), nm1 = fmaxf(m1, mx1);
        const float c0 = __expf(m0 - nm0), c1 = __expf(m1 - nm1);
        m0 = nm0; m1 = nm1;

        float ls0 = 0.f, ls1 = 0.f;
        #pragma unroll
        for (int nb = 0; nb < 8; nb++) {
            const float p0 = __expf(sacc[nb][0] - m0);
            const float p1 = __expf(sacc[nb][1] - m0);
            const float p2 = __expf(sacc[nb][2] - m1);
            const float p3 = __expf(sacc[nb][3] - m1);
            ls0 += p0 + p1;
            ls1 += p2 + p3;
            const int c = nb * 8 + 2 * tg;
            float2 w0, w1;
            w0.x = __uint_as_float(f2tf(p0));
            w0.y = __uint_as_float(f2tf(p1));
            w1.x = __uint_as_float(f2tf(p2));
            w1.y = __uint_as_float(f2tf(p3));
            *(float2*)&Pw[gr * AP + c] = w0;
            *(float2*)&Pw[(gr + 8) * AP + c] = w1;
        }
        ls0 += __shfl_xor_sync(0xffffffffu, ls0, 1);
        ls0 += __shfl_xor_sync(0xffffffffu, ls0, 2);
        ls1 += __shfl_xor_sync(0xffffffffu, ls1, 1);
        ls1 += __shfl_xor_sync(0xffffffffu, ls1, 2);
        l0 = l0 * c0 + ls0;
        l1 = l1 * c1 + ls1;
        #pragma unroll
        for (int nb = 0; nb < 8; nb++) {
            oacc[nb][0] *= c0; oacc[nb][1] *= c0;
            oacc[nb][2] *= c1; oacc[nb][3] *= c1;
        }
        __syncwarp();

        // ---- O += P V (64 MMAs) ----
        #pragma unroll
        for (int kb = 0; kb < 8; kb++) {
            unsigned af[4];
            af[0] = __float_as_uint(Pw[gr * AP + kb * 8 + tg]);
            af[1] = __float_as_uint(Pw[(gr + 8) * AP + kb * 8 + tg]);
            af[2] = __float_as_uint(Pw[gr * AP + kb * 8 + tg + 4]);
            af[3] = __float_as_uint(Pw[(gr + 8) * AP + kb * 8 + tg + 4]);
            #pragma unroll
            for (int nb = 0; nb < 8; nb++) {
                unsigned b0 = __float_as_uint(Vs[(nb * 8 + gr) * AP + kb * 8 + tg]);
                unsigned b1 = __float_as_uint(Vs[(nb * 8 + gr) * AP + kb * 8 + tg + 4]);
                mma8(oacc[nb], af, b0, b1);
            }
        }
    }

    // ---- epilogue ----
    const float inv0 = 1.f / l0, inv1 = 1.f / l1;
    float* out0 = att + (size_t)(b * Ss + i0) * Dd + h * HD;
    float* out1 = out0 + (size_t)8 * Dd;
    #pragma unroll
    for (int nb = 0; nb < 8; nb++) {
        const int c = nb * 8 + 2 * tg;
        float2 o0, o1;
        o0.x = oacc[nb][0] * inv0;
        o0.y = oacc[nb][1] * inv0;
        o1.x = oacc[nb][2] * inv1;
        o1.y = oacc[nb][3] * inv1;
        *(float2*)&out0[c] = o0;
        *(float2*)&out1[c] = o1;
    }
}

// ===========================================================================
// Launch
// ===========================================================================
extern "C" void kernel_launch(void* const* d_in, const int* in_sizes, int n_in,
                              void* d_out, int out_size) {
    const float* x     = (const float*)d_in[0];
    const float* mask  = (const float*)d_in[1];
    const float* W_qkv = (const float*)d_in[2];
    const float* b_qkv = (const float*)d_in[3];
    const float* W_o   = (const float*)d_in[4];
    const float* b_o   = (const float*)d_in[5];
    float* out = (float*)d_out;

    float* qkv_ptr = nullptr;
    float* att_ptr = nullptr;
    cudaGetSymbolAddress((void**)&qkv_ptr, g_qkv);
    cudaGetSymbolAddress((void**)&att_ptr, g_att);

    cudaFuncSetAttribute(gemm_tf32, cudaFuncAttributeMaxDynamicSharedMemorySize,
                         GEMM_SMEM_BYTES);
    cudaFuncSetAttribute(flash_mma, cudaFuncAttributeMaxDynamicSharedMemorySize,
                         ATT_SMEM_BYTES);

    // 1) QKV projection
    gemm_tf32<<<dim3(3 * Dd / 128, Mrows / 128), 512, GEMM_SMEM_BYTES>>>(
        x, W_qkv, b_qkv, qkv_ptr, Mrows, 3 * Dd, Dd);

    // 2) Flash attention (tensorized)
    flash_mma<<<dim3(Ss / 128, Hh, Bb), 256, ATT_SMEM_BYTES>>>(
        qkv_ptr, mask, att_ptr);

    // 3) Output projection
    gemm_tf32<<<dim3(Dd / 128, Mrows / 128), 512, GEMM_SMEM_BYTES>>>(
        att_ptr, W_o, b_o, out, Mrows, Dd, Dd);
}